// round 4
// baseline (speedup 1.0000x reference)
#include <cuda_runtime.h>
#include <cstdint>

// KroneckerLinear: out = x @ kron(f1,f2)^T + bias, per row Y = f1 @ X @ f2^T
// (1024 FMA/row). Persistent blocks, double-buffered cp.async pipeline,
// packed f32x2 FMA, 2 threads per row with in-warp shuffle exchange of T.

#define TILE_ROWS 128
#define THREADS   256
#define PITCH4    17                      // float4 pitch per row (68 floats)
#define BUF_F4    (TILE_ROWS * PITCH4)    // 2176 float4 = 34816 B per buffer

typedef unsigned long long u64;

__device__ __forceinline__ uint32_t s2u(const void* p) {
    uint32_t a;
    asm("{ .reg .u64 t; cvta.to.shared.u64 t, %1; cvt.u32.u64 %0, t; }"
        : "=r"(a) : "l"(p));
    return a;
}
__device__ __forceinline__ void cp16(uint32_t s, const void* g) {
    asm volatile("cp.async.cg.shared.global [%0], [%1], 16;" :: "r"(s), "l"(g));
}
__device__ __forceinline__ void cp_commit() {
    asm volatile("cp.async.commit_group;");
}
__device__ __forceinline__ void cp_wait1() {
    asm volatile("cp.async.wait_group 1;");
}
__device__ __forceinline__ u64 pack2(float lo, float hi) {
    u64 r; asm("mov.b64 %0, {%1, %2};" : "=l"(r) : "f"(lo), "f"(hi)); return r;
}
__device__ __forceinline__ void fma2(u64& d, u64 a, u64 b) {
    asm("fma.rn.f32x2 %0, %1, %2, %0;" : "+l"(d) : "l"(a), "l"(b));
}

__global__ __launch_bounds__(THREADS, 2)
void kron_kernel(const float4* __restrict__ gx,
                 float4*       __restrict__ gout,
                 const float*  __restrict__ f1,
                 const float*  __restrict__ f2,
                 const float*  __restrict__ bias,
                 long long nrows)
{
    extern __shared__ float4 dbuf[];          // 2 * BUF_F4 float4
    __shared__ u64 f1t[64];                   // [i*8+k] = (f1[i,k], f1[i,k])
    __shared__ u64 g2t[32];                   // [l*4+p] = (f2[2p,l], f2[2p+1,l])
    __shared__ u64 bt[32];                    // bias pairs [i*4+p]

    const int tid = threadIdx.x;
    if (tid < 32) {
        int l = tid >> 2, p = tid & 3;
        g2t[tid] = pack2(f2[(2 * p) * 8 + l], f2[(2 * p + 1) * 8 + l]);
        bt[tid]  = pack2(bias[2 * tid], bias[2 * tid + 1]);
    }
    if (tid < 64) f1t[tid] = pack2(f1[tid], f1[tid]);
    __syncthreads();

    const long long ntiles = (nrows + TILE_ROWS - 1) / TILE_ROWS;
    const uint32_t sb0 = s2u(dbuf);
    const uint32_t sb1 = s2u(dbuf + BUF_F4);

    long long tile = blockIdx.x;

    // ---- prologue: stage first tile into buffer 0 ----
    if (tile < ntiles) {
        const float4* src = gx + tile * (TILE_ROWS * 16);
        long long base = tile * TILE_ROWS;
        #pragma unroll
        for (int i = 0; i < 8; i++) {
            int f = tid + i * THREADS;
            int r = f >> 4;
            if (base + r < nrows)
                cp16(sb0 + (uint32_t)(f + r) * 16u, src + f);
        }
    }
    cp_commit();

    const int r = tid >> 1;          // row within tile
    const int q = tid & 1;           // half-worker of the row

    int b = 0;
    while (tile < ntiles) {
        const long long nt = tile + gridDim.x;

        // ---- prefetch next tile into the other buffer ----
        if (nt < ntiles) {
            const float4* src = gx + nt * (TILE_ROWS * 16);
            long long base = nt * TILE_ROWS;
            uint32_t sbn = b ? sb0 : sb1;
            #pragma unroll
            for (int i = 0; i < 8; i++) {
                int f = tid + i * THREADS;
                int rr = f >> 4;
                if (base + rr < nrows)
                    cp16(sbn + (uint32_t)(f + rr) * 16u, src + f);
            }
        }
        cp_commit();
        cp_wait1();                 // current tile's group complete
        __syncthreads();

        float4* xrow = dbuf + b * BUF_F4 + r * PITCH4;
        const bool active = (tile * TILE_ROWS + r) < nrows;

        u64 y[16];
        if (active) {
            // ---- load own 4 X rows (k in {2q,2q+1,2q+4,2q+5}) ----
            float xs[32];
            #pragma unroll
            for (int m = 0; m < 4; m++) {
                const int k = 2 * q + (m & 1) + ((m >> 1) << 2);
                float4 a = xrow[2 * k];
                float4 c = xrow[2 * k + 1];
                xs[m * 8 + 0] = a.x; xs[m * 8 + 1] = a.y;
                xs[m * 8 + 2] = a.z; xs[m * 8 + 3] = a.w;
                xs[m * 8 + 4] = c.x; xs[m * 8 + 5] = c.y;
                xs[m * 8 + 6] = c.z; xs[m * 8 + 7] = c.w;
            }

            // ---- T[k][p] = sum_l X[k,l] * f2-pair(l,p) ----
            u64 t[16];
            #pragma unroll
            for (int m = 0; m < 16; m++) t[m] = 0;
            #pragma unroll
            for (int l = 0; l < 8; l++) {
                u64 g0 = g2t[l * 4 + 0];
                u64 g1 = g2t[l * 4 + 1];
                u64 g2 = g2t[l * 4 + 2];
                u64 g3 = g2t[l * 4 + 3];
                #pragma unroll
                for (int m = 0; m < 4; m++) {
                    u64 x2 = pack2(xs[m * 8 + l], xs[m * 8 + l]);
                    fma2(t[m * 4 + 0], x2, g0);
                    fma2(t[m * 4 + 1], x2, g1);
                    fma2(t[m * 4 + 2], x2, g2);
                    fma2(t[m * 4 + 3], x2, g3);
                }
            }

            // ---- y init with bias (own i set) ----
            #pragma unroll
            for (int mi = 0; mi < 4; mi++) {
                const int i = 2 * q + (mi & 1) + ((mi >> 1) << 2);
                y[mi * 4 + 0] = bt[i * 4 + 0];
                y[mi * 4 + 1] = bt[i * 4 + 1];
                y[mi * 4 + 2] = bt[i * 4 + 2];
                y[mi * 4 + 3] = bt[i * 4 + 3];
            }

            // ---- own-k accumulation ----
            #pragma unroll
            for (int m = 0; m < 4; m++) {
                const int k = 2 * q + (m & 1) + ((m >> 1) << 2);
                #pragma unroll
                for (int mi = 0; mi < 4; mi++) {
                    const int i = 2 * q + (mi & 1) + ((mi >> 1) << 2);
                    u64 a2 = f1t[i * 8 + k];
                    fma2(y[mi * 4 + 0], a2, t[m * 4 + 0]);
                    fma2(y[mi * 4 + 1], a2, t[m * 4 + 1]);
                    fma2(y[mi * 4 + 2], a2, t[m * 4 + 2]);
                    fma2(y[mi * 4 + 3], a2, t[m * 4 + 3]);
                }
            }

            // ---- partner-k accumulation via butterfly shuffle ----
            #pragma unroll
            for (int m = 0; m < 4; m++) {
                u64 p0 = __shfl_xor_sync(0xffffffffu, t[m * 4 + 0], 1);
                u64 p1 = __shfl_xor_sync(0xffffffffu, t[m * 4 + 1], 1);
                u64 p2 = __shfl_xor_sync(0xffffffffu, t[m * 4 + 2], 1);
                u64 p3 = __shfl_xor_sync(0xffffffffu, t[m * 4 + 3], 1);
                const int k = 2 * (q ^ 1) + (m & 1) + ((m >> 1) << 2);
                #pragma unroll
                for (int mi = 0; mi < 4; mi++) {
                    const int i = 2 * q + (mi & 1) + ((mi >> 1) << 2);
                    u64 a2 = f1t[i * 8 + k];
                    fma2(y[mi * 4 + 0], a2, p0);
                    fma2(y[mi * 4 + 1], a2, p1);
                    fma2(y[mi * 4 + 2], a2, p2);
                    fma2(y[mi * 4 + 3], a2, p3);
                }
            }
        } else {
            // keep shuffles convergent for inactive rows
            #pragma unroll
            for (int m = 0; m < 16; m++)
                (void)__shfl_xor_sync(0xffffffffu, (u64)0, 1);
        }

        // ---- write y into own row slot (in place) ----
        if (active) {
            ulonglong2* yr = (ulonglong2*)xrow;
            #pragma unroll
            for (int mi = 0; mi < 4; mi++) {
                const int i = 2 * q + (mi & 1) + ((mi >> 1) << 2);
                yr[2 * i]     = make_ulonglong2(y[mi * 4 + 0], y[mi * 4 + 1]);
                yr[2 * i + 1] = make_ulonglong2(y[mi * 4 + 2], y[mi * 4 + 3]);
            }
        }
        __syncthreads();

        // ---- coalesced store ----
        {
            float4* dst = gout + tile * (TILE_ROWS * 16);
            const float4* sbuf = dbuf + b * BUF_F4;
            long long base = tile * TILE_ROWS;
            #pragma unroll
            for (int i = 0; i < 8; i++) {
                int f = tid + i * THREADS;
                int rr = f >> 4;
                if (base + rr < nrows)
                    dst[f] = sbuf[f + rr];
            }
        }
        __syncthreads();            // buffer b reused by next prefetch

        tile = nt;
        b ^= 1;
    }
}

extern "C" void kernel_launch(void* const* d_in, const int* in_sizes, int n_in,
                              void* d_out, int out_size)
{
    const float* x    = (const float*)d_in[0];
    const float* f1   = (const float*)d_in[1];
    const float* f2   = (const float*)d_in[2];
    const float* bias = (const float*)d_in[3];
    float* out = (float*)d_out;

    long long nrows = (long long)in_sizes[0] / 64;

    const int smem_bytes = 2 * BUF_F4 * sizeof(float4);   // 69632
    cudaFuncSetAttribute(kron_kernel,
                         cudaFuncAttributeMaxDynamicSharedMemorySize, smem_bytes);

    int grid = 2 * 148;     // persistent: 2 blocks per SM
    kron_kernel<<<grid, THREADS, smem_bytes>>>(
        (const float4*)x, (float4*)out, f1, f2, bias, nrows);
}